// round 1
// baseline (speedup 1.0000x reference)
#include <cuda_runtime.h>
#include <cuda_bf16.h>

#define N_NODES 100000
#define N_EDGES 1600000
#define DIM 128

// Scratch for h = x @ W^T  (51.2 MB, __device__ global per allocation rules)
__device__ float g_h[(size_t)N_NODES * DIM];

// ---------------------------------------------------------------------------
// Zero the output (it is poisoned to 0xAA before timing).
// ---------------------------------------------------------------------------
__global__ void zero_kernel(float4* __restrict__ out, int n4) {
    int i = blockIdx.x * blockDim.x + threadIdx.x;
    if (i < n4) out[i] = make_float4(0.f, 0.f, 0.f, 0.f);
}

// ---------------------------------------------------------------------------
// GEMM: g_h[n][o] = sum_k x[n][k] * W[o][k]
// W staged fully in shared (128 x 132 padded -> conflict-free .128 reads).
// Block = 256 threads = 8 warps. Warp w handles 8 rows (row0 + w*8 ..),
// lane c handles cols {c, c+32, c+64, c+96}. x reads are warp-broadcast (L1).
// ---------------------------------------------------------------------------
__global__ __launch_bounds__(256) void gemm_kernel(const float* __restrict__ x,
                                                   const float* __restrict__ W) {
    extern __shared__ float w_s[]; // [128][132]
    const int tid = threadIdx.x;

    // Stage W: 128*128 floats = 4096 float4, 16 per thread.
    for (int idx = tid; idx < 128 * 32; idx += 256) {
        int row = idx >> 5;
        int c4  = idx & 31;
        float4 v = *reinterpret_cast<const float4*>(W + row * 128 + c4 * 4);
        *reinterpret_cast<float4*>(w_s + row * 132 + c4 * 4) = v;
    }
    __syncthreads();

    const int cid = tid & 31;   // lane -> column group
    const int rid = tid >> 5;   // warp -> row group
    const long row0 = (long)blockIdx.x * 64 + (long)rid * 8;

    // Clamp row pointers for the tail block so loads stay in-bounds;
    // writes are guarded by the true row index.
    const float* xp[8];
#pragma unroll
    for (int r = 0; r < 8; r++) {
        long row = row0 + r;
        if (row > N_NODES - 1) row = N_NODES - 1;
        xp[r] = x + row * DIM;
    }

    float acc[8][4];
#pragma unroll
    for (int r = 0; r < 8; r++)
#pragma unroll
        for (int j = 0; j < 4; j++) acc[r][j] = 0.f;

#pragma unroll 4
    for (int k4 = 0; k4 < 32; ++k4) {
        float4 wv[4];
#pragma unroll
        for (int j = 0; j < 4; j++)
            wv[j] = *reinterpret_cast<const float4*>(w_s + (cid + 32 * j) * 132 + k4 * 4);
#pragma unroll
        for (int r = 0; r < 8; r++) {
            float4 xv = *reinterpret_cast<const float4*>(xp[r] + k4 * 4);
#pragma unroll
            for (int j = 0; j < 4; j++) {
                acc[r][j] += xv.x * wv[j].x;
                acc[r][j] += xv.y * wv[j].y;
                acc[r][j] += xv.z * wv[j].z;
                acc[r][j] += xv.w * wv[j].w;
            }
        }
    }

#pragma unroll
    for (int r = 0; r < 8; r++) {
        long row = row0 + r;
        if (row < N_NODES) {
            float* hp = g_h + row * DIM;
#pragma unroll
            for (int j = 0; j < 4; j++) hp[cid + 32 * j] = acc[r][j];
        }
    }
}

// ---------------------------------------------------------------------------
// Edge scatter: one warp per edge. Lane l handles floats [4l, 4l+4).
// gather h[src] (float4, coalesced 512B/warp), scale, red.global.add.v4.f32
// into out[dst] (no-return reduction, 4x fewer LTS atomic ops than scalar).
// ---------------------------------------------------------------------------
__global__ __launch_bounds__(256) void edge_kernel(const float* __restrict__ vals,
                                                   const int* __restrict__ src,
                                                   const int* __restrict__ dst,
                                                   float* __restrict__ out) {
    long gtid = (long)blockIdx.x * 256 + threadIdx.x;
    int e    = (int)(gtid >> 5);
    int lane = threadIdx.x & 31;
    if (e >= N_EDGES) return;

    int   s = __ldg(src + e);
    int   d = __ldg(dst + e);
    float v = __ldg(vals + e);

    float4 hv = *reinterpret_cast<const float4*>(g_h + (long)s * DIM + lane * 4);
    float* op = out + (long)d * DIM + lane * 4;

    asm volatile("red.global.add.v4.f32 [%0], {%1, %2, %3, %4};"
                 :: "l"(op), "f"(hv.x * v), "f"(hv.y * v), "f"(hv.z * v), "f"(hv.w * v)
                 : "memory");
}

// ---------------------------------------------------------------------------
// Launch. Inputs (metadata order): x, W, vals, src, dst. Output: float32.
// ---------------------------------------------------------------------------
extern "C" void kernel_launch(void* const* d_in, const int* in_sizes, int n_in,
                              void* d_out, int out_size) {
    const float* x    = (const float*)d_in[0];
    const float* W    = (const float*)d_in[1];
    const float* vals = (const float*)d_in[2];
    const int*   src  = (const int*)d_in[3];
    const int*   dst  = (const int*)d_in[4];
    float*       out  = (float*)d_out;

    const int smem = 128 * 132 * sizeof(float); // 67,584 B > 48KB default -> opt in
    cudaFuncSetAttribute(gemm_kernel, cudaFuncAttributeMaxDynamicSharedMemorySize, smem);

    // 1) zero out (poisoned by harness)
    int n4 = (N_NODES * DIM) / 4;
    zero_kernel<<<(n4 + 255) / 256, 256>>>((float4*)out, n4);

    // 2) h = x @ W^T
    gemm_kernel<<<(N_NODES + 63) / 64, 256, smem>>>(x, W);

    // 3) edge gather-scale-scatter
    long threads = (long)N_EDGES * 32;
    int blocks = (int)((threads + 255) / 256);
    edge_kernel<<<blocks, 256>>>(vals, src, dst, out);
}